// round 9
// baseline (speedup 1.0000x reference)
#include <cuda_runtime.h>
#include <cuda_bf16.h>

#define L_SEQ  2048
#define BATCH  2
#define DMODEL 1024
#define NHEADS 16
#define DK     64
#define E3     3072
#define NROWS  4096

// fp32 QKV projection scratch: [NROWS][E3], row r = l*BATCH + b, col e = h*192 + {q,k,v}
__device__ float g_qkv[NROWS * E3];

// bf16 hi/lo splits of X and W for the projection GEMM
__device__ __align__(16) __nv_bfloat16 g_xhi[NROWS * DMODEL];
__device__ __align__(16) __nv_bfloat16 g_xlo[NROWS * DMODEL];
__device__ __align__(16) __nv_bfloat16 g_whi[E3 * DMODEL];
__device__ __align__(16) __nv_bfloat16 g_wlo[E3 * DMODEL];

// Attention operand buffers (bf16 hi/lo).
// Q,K: [b][h][l][d] (rope applied; Q pre-scaled by 0.125*log2e). V: [b][h][d][l].
#define QKV_ELEMS (BATCH * NHEADS * L_SEQ * DK)
__device__ __align__(16) __nv_bfloat16 g_qhi[QKV_ELEMS];
__device__ __align__(16) __nv_bfloat16 g_qlo[QKV_ELEMS];
__device__ __align__(16) __nv_bfloat16 g_khi[QKV_ELEMS];
__device__ __align__(16) __nv_bfloat16 g_klo[QKV_ELEMS];
__device__ __align__(16) __nv_bfloat16 g_vhi[QKV_ELEMS];
__device__ __align__(16) __nv_bfloat16 g_vlo[QKV_ELEMS];

__constant__ float c_theta[16] = {
    1.0f,                     0.5623413251903491f,     0.31622776601683794f,   0.17782794100389228f,
    0.1f,                     0.05623413251903491f,    0.031622776601683794f,  0.017782794100389228f,
    0.01f,                    0.005623413251903491f,   0.0031622776601683794f, 0.0017782794100389228f,
    0.001f,                   0.0005623413251903491f,  0.00031622776601683794f,0.00017782794100389227f
};

// ---------------------------------------------------------------------------
// Helpers
// ---------------------------------------------------------------------------
#define MMA_BF16(C, A, B)                                                        \
    asm volatile("mma.sync.aligned.m16n8k16.row.col.f32.bf16.bf16.f32 "          \
                 "{%0,%1,%2,%3}, {%4,%5,%6,%7}, {%8,%9}, {%0,%1,%2,%3};"         \
                 : "+f"((C)[0]), "+f"((C)[1]), "+f"((C)[2]), "+f"((C)[3])        \
                 : "r"((A)[0]), "r"((A)[1]), "r"((A)[2]), "r"((A)[3]),           \
                   "r"((B)[0]), "r"((B)[1]))

__device__ __forceinline__ void ldm4(unsigned* r, unsigned a) {
    asm volatile("ldmatrix.sync.aligned.m8n8.x4.shared.b16 {%0,%1,%2,%3}, [%4];"
                 : "=r"(r[0]), "=r"(r[1]), "=r"(r[2]), "=r"(r[3]) : "r"(a));
}

__device__ __forceinline__ float ex2f(float x) {
    float r;
    asm("ex2.approx.ftz.f32 %0, %1;" : "=f"(r) : "f"(x));
    return r;
}

__device__ __forceinline__ void cp16(unsigned s, const void* g) {
    asm volatile("cp.async.ca.shared.global [%0], [%1], 16;" :: "r"(s), "l"(g));
}

__device__ __forceinline__ unsigned smem_u32(const void* p) {
    return (unsigned)__cvta_generic_to_shared(p);
}

__device__ __forceinline__ void pack_hilo(float f0, float f1, unsigned& h, unsigned& l) {
    __nv_bfloat162 hb = __floats2bfloat162_rn(f0, f1);
    float r0 = f0 - __bfloat162float(hb.x);
    float r1 = f1 - __bfloat162float(hb.y);
    __nv_bfloat162 lb = __floats2bfloat162_rn(r0, r1);
    h = *reinterpret_cast<unsigned*>(&hb);
    l = *reinterpret_cast<unsigned*>(&lb);
}

// ---------------------------------------------------------------------------
// Split kernels: fp32 -> bf16 hi + bf16 lo
// ---------------------------------------------------------------------------
__device__ __forceinline__ void split4(const float4 v, __nv_bfloat16* hi, __nv_bfloat16* lo, int i4) {
    float vs[4] = {v.x, v.y, v.z, v.w};
    unsigned hp[2], lp[2];
#pragma unroll
    for (int p = 0; p < 2; p++) pack_hilo(vs[2 * p], vs[2 * p + 1], hp[p], lp[p]);
    reinterpret_cast<uint2*>(hi)[i4] = make_uint2(hp[0], hp[1]);
    reinterpret_cast<uint2*>(lo)[i4] = make_uint2(lp[0], lp[1]);
}

__global__ void __launch_bounds__(256) split_x(const float* __restrict__ src) {
    int t = blockIdx.x * 256 + threadIdx.x;
    split4(reinterpret_cast<const float4*>(src)[t], g_xhi, g_xlo, t);
}
__global__ void __launch_bounds__(256) split_w(const float* __restrict__ src) {
    int t = blockIdx.x * 256 + threadIdx.x;
    split4(reinterpret_cast<const float4*>(src)[t], g_whi, g_wlo, t);
}

// ---------------------------------------------------------------------------
// Kernel 1: QKV projection GEMM (bf16x3 mma.sync + ldmatrix + cp.async).
// CTA tile 128x128, BK=32, 8 warps, warp tile 32x64, 2-stage double buffer.
// ---------------------------------------------------------------------------
#define KPAD 40
#define ARR_B  (128 * KPAD * 2)
#define STG_B  (4 * ARR_B)
#define QKV_SMEM (2 * STG_B)

#define G_ISSUE(KT, ST)                                                               \
    do {                                                                              \
        const int _k0 = (KT) * 32;                                                    \
        _Pragma("unroll")                                                             \
        for (int _arr = 0; _arr < 4; _arr++) {                                        \
            _Pragma("unroll")                                                         \
            for (int _rep = 0; _rep < 2; _rep++) {                                    \
                int _sub = _rep * 256 + tid;                                          \
                int _row = _sub >> 2;                                                 \
                int _ch  = _sub & 3;                                                  \
                unsigned _sp = smem0 + (ST) * STG_B + _arr * ARR_B + _row * (KPAD*2) + _ch * 16; \
                const __nv_bfloat16* _gp;                                             \
                if      (_arr == 0) _gp = g_xhi + (size_t)(r0 + _row) * DMODEL + _k0 + _ch * 8; \
                else if (_arr == 1) _gp = g_xlo + (size_t)(r0 + _row) * DMODEL + _k0 + _ch * 8; \
                else if (_arr == 2) _gp = g_whi + (size_t)(e0 + _row) * DMODEL + _k0 + _ch * 8; \
                else                _gp = g_wlo + (size_t)(e0 + _row) * DMODEL + _k0 + _ch * 8; \
                cp16(_sp, _gp);                                                       \
            }                                                                         \
        }                                                                             \
        asm volatile("cp.async.commit_group;");                                       \
    } while (0)

__global__ void __launch_bounds__(256) qkv_gemm_tc() {
    extern __shared__ __align__(16) char qsm[];
    const unsigned smem0 = smem_u32(qsm);

    const int tid   = threadIdx.x;
    const int wid   = tid >> 5;
    const int lane  = tid & 31;
    const int warpM = wid >> 1;
    const int warpN = wid & 1;
    const int r0    = blockIdx.y * 128;
    const int e0    = blockIdx.x * 128;

    const int fr = lane >> 2;
    const int fc = (lane & 3) * 2;

    const int lrA = lane & 15;
    const int lcA = (lane >> 4) << 3;
    const int lrB = (lane & 7) + ((lane >> 4) << 3);
    const int lcB = ((lane >> 3) & 1) << 3;

    float acc[2][8][4] = {};

    G_ISSUE(0, 0);
    G_ISSUE(1, 1);

    for (int kt = 0; kt < 32; kt++) {
        if (kt < 31) asm volatile("cp.async.wait_group 1;");
        else         asm volatile("cp.async.wait_group 0;");
        __syncthreads();

        const unsigned uA_hi = smem0 + (kt & 1) * STG_B;
        const unsigned uA_lo = uA_hi + ARR_B;
        const unsigned uB_hi = uA_hi + 2 * ARR_B;
        const unsigned uB_lo = uA_hi + 3 * ARR_B;

#pragma unroll
        for (int ks = 0; ks < 32; ks += 16) {
            unsigned ahi[2][4], alo[2][4], bhi[4][4], blo[4][4];
#pragma unroll
            for (int mf = 0; mf < 2; mf++) {
                const unsigned ao = (unsigned)(((warpM * 32 + mf * 16 + lrA) * KPAD + ks + lcA) * 2);
                ldm4(ahi[mf], uA_hi + ao);
                ldm4(alo[mf], uA_lo + ao);
            }
#pragma unroll
            for (int g4 = 0; g4 < 4; g4++) {
                const unsigned bo = (unsigned)(((warpN * 64 + g4 * 16 + lrB) * KPAD + ks + lcB) * 2);
                ldm4(bhi[g4], uB_hi + bo);
                ldm4(blo[g4], uB_lo + bo);
            }
#pragma unroll
            for (int mf = 0; mf < 2; mf++)
#pragma unroll
                for (int nf = 0; nf < 8; nf++) {
                    const unsigned* bh = &bhi[nf >> 1][(nf & 1) * 2];
                    const unsigned* bl = &blo[nf >> 1][(nf & 1) * 2];
                    MMA_BF16(acc[mf][nf], ahi[mf], bh);
                    MMA_BF16(acc[mf][nf], ahi[mf], bl);
                    MMA_BF16(acc[mf][nf], alo[mf], bh);
                }
        }
        __syncthreads();
        if (kt + 2 < 32) G_ISSUE(kt + 2, kt & 1);
    }

#pragma unroll
    for (int mf = 0; mf < 2; mf++)
#pragma unroll
        for (int nf = 0; nf < 8; nf++) {
            const int row = r0 + warpM * 32 + mf * 16 + fr;
            const int col = e0 + warpN * 64 + nf * 8 + fc;
            *reinterpret_cast<float2*>(&g_qkv[(size_t)row * E3 + col]) =
                make_float2(acc[mf][nf][0], acc[mf][nf][1]);
            *reinterpret_cast<float2*>(&g_qkv[(size_t)(row + 8) * E3 + col]) =
                make_float2(acc[mf][nf][2], acc[mf][nf][3]);
        }
}

// ---------------------------------------------------------------------------
// Kernel 2: rope + split for Q and K -> bf16 hi/lo, layout [b][h][l][d].
// ---------------------------------------------------------------------------
#define QSCALE 0.1803368801111243f   // 0.125 * log2(e)

__global__ void __launch_bounds__(256) prep_qk() {
    const int t   = blockIdx.x * 256 + threadIdx.x;
    const int j   = t & 15;
    const int sqk = (t >> 4) & 1;
    const int h   = (t >> 5) & 15;
    const int r   = t >> 9;
    const int l   = r >> 1;
    const int b   = r & 1;

    const float* base = g_qkv + (size_t)r * E3 + h * 192 + sqk * 64;
    float x0 = base[j];
    float x1 = base[j + 16];
    float p0 = base[j + 32];
    float p1 = base[j + 48];

    float ang = (float)l * c_theta[j];
    float sn, cs;
    sincosf(ang, &sn, &cs);
    float y0 = x0 * cs - x1 * sn;
    float y1 = x1 * cs + x0 * sn;

    const float sc = sqk ? 1.0f : QSCALE;
    y0 *= sc; y1 *= sc; p0 *= sc; p1 *= sc;

    const size_t dst = ((size_t)(b * NHEADS + h) * L_SEQ + l) * DK;
    __nv_bfloat16* dh = (sqk ? g_khi : g_qhi) + dst;
    __nv_bfloat16* dl = (sqk ? g_klo : g_qlo) + dst;

    float vals[4] = {y0, y1, p0, p1};
    int   ds[4]   = {j, j + 16, j + 32, j + 48};
#pragma unroll
    for (int i = 0; i < 4; i++) {
        __nv_bfloat16 hi = __float2bfloat16_rn(vals[i]);
        dh[ds[i]] = hi;
        dl[ds[i]] = __float2bfloat16_rn(vals[i] - __bfloat162float(hi));
    }
}

// ---------------------------------------------------------------------------
// Kernel 3: V transpose + split -> bf16 hi/lo, layout [b][h][d][l].
// ---------------------------------------------------------------------------
__global__ void __launch_bounds__(128) prep_v() {
    __shared__ float s[64][68];
    const int tile = blockIdx.x, h = blockIdx.y, b = blockIdx.z;
    const int tid = threadIdx.x;

#pragma unroll
    for (int i = 0; i < 8; i++) {
        int id  = i * 128 + tid;
        int row = id >> 4;
        int c4  = id & 15;
        const float* g = g_qkv + (size_t)((tile * 64 + row) * 2 + b) * E3 + h * 192 + 128 + c4 * 4;
        float4 v = *reinterpret_cast<const float4*>(g);
        s[row][c4 * 4 + 0] = v.x; s[row][c4 * 4 + 1] = v.y;
        s[row][c4 * 4 + 2] = v.z; s[row][c4 * 4 + 3] = v.w;
    }
    __syncthreads();

    const int d = tid & 63, part = tid >> 6;
    const size_t ob = ((size_t)(b * NHEADS + h) * DK + d) * L_SEQ + tile * 64 + part * 32;

#pragma unroll
    for (int kc = 0; kc < 4; kc++) {
        unsigned hw[4], lw[4];
#pragma unroll
        for (int p = 0; p < 4; p++) {
            float v0 = s[part * 32 + kc * 8 + p * 2 + 0][d];
            float v1 = s[part * 32 + kc * 8 + p * 2 + 1][d];
            pack_hilo(v0, v1, hw[p], lw[p]);
        }
        *reinterpret_cast<uint4*>(g_vhi + ob + kc * 8) = make_uint4(hw[0], hw[1], hw[2], hw[3]);
        *reinterpret_cast<uint4*>(g_vlo + ob + kc * 8) = make_uint4(lw[0], lw[1], lw[2], lw[3]);
    }
}

// ---------------------------------------------------------------------------
// Kernel 4: tensor-core flash attention, split-KV warp groups.
// 256 threads = 2 groups of 4 warps. Group g processes KV tiles [g*16, g*16+16),
// own double-buffered pipeline + named barrier. Group 1 spills partials to smem;
// group 0 merges (flash split-k combine) and writes out.
// smem (bf16 elems): Qhi 128x72 @0, Qlo @9216, 4 KV stages of 18432 @18432+s*18432.
// ---------------------------------------------------------------------------
#define ATTN_SMEM_BYTES (5 * 18432 * 2)   // 184320

__global__ void __launch_bounds__(256) attn_tc(float* __restrict__ out) {
    extern __shared__ __align__(16) __nv_bfloat16 sm[];
    const unsigned smem_base = smem_u32(sm);

    const int tid  = threadIdx.x;
    const int w    = tid >> 5;
    const int grp  = w >> 2;          // 0 or 1
    const int wg   = w & 3;           // warp within group
    const int lane = tid & 31;
    const int g    = lane >> 2;
    const int tg   = lane & 3;
    const int ltid = tid & 127;       // thread id within group

    const int lrA = lane & 15;
    const int lcA = (lane >> 4) << 3;
    const int lrB = (lane & 7) + ((lane >> 4) << 3);
    const int lcB = ((lane >> 3) & 1) << 3;

    const int q0 = blockIdx.x * 128;
    const int h  = blockIdx.y;
    const int b  = blockIdx.z;
    const int hb = b * NHEADS + h;

    const size_t qkbase = (size_t)hb * L_SEQ * DK;
    const size_t vbase  = (size_t)hb * DK * L_SEQ;

    // ---- Q tile loads (all 256 threads), own commit group ----
#pragma unroll
    for (int i = 0; i < 8; i++) {
        int id  = i * 256 + tid;
        int rid = (id >> 3) & 127;
        int ch  = id & 7;
        const __nv_bfloat16* gp = (i < 4 ? g_qhi : g_qlo) + qkbase + (size_t)(q0 + rid) * DK + ch * 8;
        unsigned sp = smem_base + ((i < 4 ? 0 : 9216) + rid * 72 + ch * 8) * 2;
        cp16(sp, gp);
    }
    asm volatile("cp.async.commit_group;");

    // KV tile issue: 16 chunks per group-thread (2048 chunks of 16B per tile).
#define ISSUE_TILE(T, BUF)                                                            \
    do {                                                                              \
        _Pragma("unroll")                                                             \
        for (int i = 0; i < 16; i++) {                                                \
            int id  = i * 128 + ltid;                                                 \
            int arr = i >> 2;                                                         \
            int rid = (id >> 3) & 63;                                                 \
            int ch  = id & 7;                                                         \
            const __nv_bfloat16* gp;                                                  \
            if (arr == 0)      gp = g_khi + qkbase + (size_t)((T) * 64 + rid) * DK + ch * 8; \
            else if (arr == 1) gp = g_klo + qkbase + (size_t)((T) * 64 + rid) * DK + ch * 8; \
            else if (arr == 2) gp = g_vhi + vbase + (size_t)rid * L_SEQ + (T) * 64 + ch * 8; \
            else               gp = g_vlo + vbase + (size_t)rid * L_SEQ + (T) * 64 + ch * 8; \
            unsigned sp = smem_base + (18432 + (BUF) * 18432 + arr * 4608 + rid * 72 + ch * 8) * 2; \
            cp16(sp, gp);                                                             \
        }                                                                             \
        asm volatile("cp.async.commit_group;");                                       \
    } while (0)

    const int t0 = grp * 16;
    ISSUE_TILE(t0, grp * 2);
    // Ensure Q (oldest group) is complete and visible to ALL threads.
    asm volatile("cp.async.wait_group 1;");
    __syncthreads();

    float o[2][8][4] = {};
    float mrow[2][2] = {{-1e30f, -1e30f}, {-1e30f, -1e30f}};
    float lrow[2][2] = {};

    const int rb0 = wg * 32;
    const int barid = grp + 1;

    for (int lt = 0; lt < 16; lt++) {
        const int buf = grp * 2 + (lt & 1);
        if (lt < 15) {
            ISSUE_TILE(t0 + lt + 1, grp * 2 + ((lt + 1) & 1));
            asm volatile("cp.async.wait_group 1;");
        } else {
            asm volatile("cp.async.wait_group 0;");
        }
        asm volatile("bar.sync %0, 128;" :: "r"(barid) : "memory");

        const unsigned uQh = smem_base;
        const unsigned uQl = smem_base + 9216 * 2;
        const unsigned uKh = smem_base + (18432 + buf * 18432) * 2;
        const unsigned uKl = uKh + 4608 * 2;
        const unsigned uVh = uKh + 9216 * 2;
        const unsigned uVl = uKh + 13824 * 2;

        // ---- S = Q K^T (bf16x3) ----
        float s[2][8][4] = {};
#pragma unroll
        for (int kf = 0; kf < 4; kf++) {
            unsigned ah[2][4], al[2][4], kh[4][4], kl[4][4];
#pragma unroll
            for (int mf = 0; mf < 2; mf++) {
                const unsigned ao = (unsigned)(((rb0 + mf * 16 + lrA) * 72 + kf * 16 + lcA) * 2);
                ldm4(ah[mf], uQh + ao);
                ldm4(al[mf], uQl + ao);
            }
#pragma unroll
            for (int g4 = 0; g4 < 4; g4++) {
                const unsigned bo = (unsigned)(((g4 * 16 + lrB) * 72 + kf * 16 + lcB) * 2);
                ldm4(kh[g4], uKh + bo);
                ldm4(kl[g4], uKl + bo);
            }
#pragma unroll
            for (int nf = 0; nf < 8; nf++) {
                const unsigned* bh = &kh[nf >> 1][(nf & 1) * 2];
                const unsigned* bl = &kl[nf >> 1][(nf & 1) * 2];
#pragma unroll
                for (int mf = 0; mf < 2; mf++) {
                    MMA_BF16(s[mf][nf], ah[mf], bh);
                    MMA_BF16(s[mf][nf], ah[mf], bl);
                    MMA_BF16(s[mf][nf], al[mf], bh);
                }
            }
        }

        // ---- online softmax (log2 domain) ----
        unsigned ph[2][4][4], pl[2][4][4];
#pragma unroll
        for (int mf = 0; mf < 2; mf++) {
            float mx0 = -1e30f, mx1 = -1e30f;
#pragma unroll
            for (int nf = 0; nf < 8; nf++) {
                mx0 = fmaxf(mx0, fmaxf(s[mf][nf][0], s[mf][nf][1]));
                mx1 = fmaxf(mx1, fmaxf(s[mf][nf][2], s[mf][nf][3]));
            }
            mx0 = fmaxf(mx0, __shfl_xor_sync(0xffffffffu, mx0, 1));
            mx0 = fmaxf(mx0, __shfl_xor_sync(0xffffffffu, mx0, 2));
            mx1 = fmaxf(mx1, __shfl_xor_sync(0xffffffffu, mx1, 1));
            mx1 = fmaxf(mx1, __shfl_xor_sync(0xffffffffu, mx1, 2));

            float mn0 = fmaxf(mrow[mf][0], mx0);
            float mn1 = fmaxf(mrow[mf][1], mx1);
            float sc0 = ex2f(mrow[mf][0] - mn0);
            float sc1 = ex2f(mrow[mf][1] - mn1);
            mrow[mf][0] = mn0;
            mrow[mf][1] = mn1;

            float rs0 = 0.f, rs1 = 0.f;
#pragma unroll
            for (int nf = 0; nf < 8; nf++) {
                s[mf][nf][0] = ex2f(s[mf][nf][0] - mn0);
                s[mf][nf][1] = ex2f(s[mf][nf][1] - mn0);
                s[mf][nf][2] = ex2f(s[mf][nf][2] - mn1);
                s[mf][nf][3] = ex2f(s[mf][nf][3] - mn1);
                rs0 += s[mf][nf][0] + s[mf][nf][1];
                rs1 += s[mf][nf][2] + s[mf][nf][3];
            }
            rs0 += __shfl_xor_sync(0xffffffffu, rs0, 1);
            rs0 += __shfl_xor_sync(0xffffffffu, rs0, 2);
            rs1 += __shfl_xor_sync(0xffffffffu, rs1, 1);
            rs1 += __shfl_xor_sync(0xffffffffu, rs1, 2);
            lrow[mf][0] = lrow[mf][0] * sc0 + rs0;
            lrow[mf][1] = lrow[mf][1] * sc1 + rs1;

#pragma unroll
            for (int nf = 0; nf < 8; nf++) {
                o[mf][nf][0] *= sc0; o[mf][nf][1] *= sc0;
                o[mf][nf][2] *= sc1; o[mf][nf][3] *= sc1;
            }

#pragma unroll
            for (int kf = 0; kf < 4; kf++) {
                const int n0 = 2 * kf, n1 = 2 * kf + 1;
                pack_hilo(s[mf][n0][0], s[mf][n0][1], ph[mf][kf][0], pl[mf][kf][0]);
                pack_hilo(s[mf][n0][2], s[mf][n0][3], ph[mf][kf][1], pl[mf][kf][1]);
                pack_hilo(s[mf][n1][0], s[mf][n1][1], ph[mf][kf][2], pl[mf][kf][2]);
                pack_hilo(s[mf][n1][2], s[mf][n1][3], ph[mf][kf][3], pl[mf][kf][3]);
            }
        }

        // ---- O += P V (bf16x3) ----
#pragma unroll
        for (int kf = 0; kf < 4; kf++) {
            unsigned vh[4][4], vl[4][4];
#pragma unroll
            for (int g4 = 0; g4 < 4; g4++) {
                const unsigned bo = (unsigned)(((g4 * 16 + lrB) * 72 + kf * 16 + lcB) * 2);
                ldm4(vh[g4], uVh + bo);
                ldm4(vl[g4], uVl + bo);
            }
#pragma unroll
            for (int nf = 0; nf < 8; nf++) {
                const unsigned* bh = &vh[nf >> 1][(nf & 1) * 2];
                const unsigned* bl = &vl[nf >> 1][(nf & 1) * 2];
#pragma unroll
                for (int mf = 0; mf < 2; mf++) {
                    MMA_BF16(o[mf][nf], ph[mf][kf], bh);
                    MMA_BF16(o[mf][nf], pl[mf][kf], bh);
                    MMA_BF16(o[mf][nf], ph[mf][kf], bl);
                }
            }
        }
        asm volatile("bar.sync %0, 128;" :: "r"(barid) : "memory");
    }

    // ---- split-KV merge ----
    // Group 1 spills (O, m, l) into smem (over group-0's dead KV stages);
    // group 0 combines and writes gmem.
    float* sO = reinterpret_cast<float*>(sm + 18432);        // [128][68]
    float* sM = sO + 128 * 68;                               // [128]
    float* sL = sM + 128;                                    // [128]

    __syncthreads();
    if (grp == 1) {
#pragma unroll
        for (int mf = 0; mf < 2; mf++) {
            const int rA = rb0 + mf * 16 + g;
            const int rB = rA + 8;
#pragma unroll
            for (int nf = 0; nf < 8; nf++) {
                const int col = nf * 8 + tg * 2;
                *reinterpret_cast<float2*>(&sO[rA * 68 + col]) = make_float2(o[mf][nf][0], o[mf][nf][1]);
                *reinterpret_cast<float2*>(&sO[rB * 68 + col]) = make_float2(o[mf][nf][2], o[mf][nf][3]);
            }
            if (tg == 0) {
                sM[rA] = mrow[mf][0]; sL[rA] = lrow[mf][0];
                sM[rB] = mrow[mf][1]; sL[rB] = lrow[mf][1];
            }
        }
    }
    __syncthreads();
    if (grp == 0) {
#pragma unroll
        for (int mf = 0; mf < 2; mf++) {
            const int rA = rb0 + mf * 16 + g;
            const int rB = rA + 8;
            const float m1A = sM[rA], m1B = sM[rB];
            const float l1A = sL[rA], l1B = sL[rB];
            const float mmA = fmaxf(mrow[mf][0], m1A);
            const float mmB = fmaxf(mrow[mf][1], m1B);
            const float f0A = ex2f(mrow[mf][0] - mmA), f1A = ex2f(m1A - mmA);
            const float f0B = ex2f(mrow[mf][1] - mmB), f1B = ex2f(m1B - mmB);
            const float invA = 1.0f / (lrow[mf][0] * f0A + l1A * f1A);
            const float invB = 1.0f / (lrow[mf][1] * f0B + l1B * f1B);
#pragma unroll
            for (int nf = 0; nf < 8; nf++) {
                const int col = nf * 8 + tg * 2;
                const float2 oA = *reinterpret_cast<const float2*>(&sO[rA * 68 + col]);
                const float2 oB = *reinterpret_cast<const float2*>(&sO[rB * 68 + col]);
                const int gcol = h * 64 + col;
                *reinterpret_cast<float2*>(out + (size_t)((q0 + rA) * 2 + b) * DMODEL + gcol) =
                    make_float2((o[mf][nf][0] * f0A + oA.x * f1A) * invA,
                                (o[mf][nf][1] * f0A + oA.y * f1A) * invA);
                *reinterpret_cast<float2*>(out + (size_t)((q0 + rB) * 2 + b) * DMODEL + gcol) =
                    make_float2((o[mf][nf][2] * f0B + oB.x * f1B) * invB,
                                (o[mf][nf][3] * f0B + oB.y * f1B) * invB);
            }
        }
    }
}

// ---------------------------------------------------------------------------
extern "C" void kernel_launch(void* const* d_in, const int* in_sizes, int n_in,
                              void* d_out, int out_size) {
    const float* x = (const float*)d_in[0];
    const float* w = (const float*)d_in[1];
    if (n_in >= 2 && in_sizes[0] == E3 * DMODEL && in_sizes[1] == NROWS * DMODEL) {
        const float* t = x; x = w; w = t;
    }
    float* out = (float*)d_out;

    static bool attr_set = false;
    if (!attr_set) {
        cudaFuncSetAttribute(attn_tc, cudaFuncAttributeMaxDynamicSharedMemorySize,
                             ATTN_SMEM_BYTES);
        cudaFuncSetAttribute(qkv_gemm_tc, cudaFuncAttributeMaxDynamicSharedMemorySize,
                             QKV_SMEM);
        attr_set = true;
    }

    split_x<<<(NROWS * DMODEL / 4) / 256, 256>>>(x);
    split_w<<<(E3 * DMODEL / 4) / 256, 256>>>(w);
    qkv_gemm_tc<<<dim3(E3 / 128, NROWS / 128), 256, QKV_SMEM>>>();
    prep_qk<<<(NROWS * NHEADS * 2 * 16) / 256, 256>>>();
    prep_v<<<dim3(L_SEQ / 64, NHEADS, BATCH), 128>>>();
    attn_tc<<<dim3(L_SEQ / 128, NHEADS, BATCH), 256, ATTN_SMEM_BYTES>>>(out);
}

// round 10
// speedup vs baseline: 1.4948x; 1.4948x over previous
#include <cuda_runtime.h>
#include <cuda_fp16.h>

#define L_SEQ  2048
#define BATCH  2
#define DMODEL 1024
#define NHEADS 16
#define DK     64
#define E3     3072
#define NROWS  4096

// fp32 QKV projection scratch: [NROWS][E3], row r = l*BATCH + b, col e = h*192 + {q,k,v}
__device__ float g_qkv[NROWS * E3];

// fp16 operands for the projection GEMM: X split hi/lo, W single (quantized)
__device__ __align__(16) __half g_xhi[NROWS * DMODEL];
__device__ __align__(16) __half g_xlo[NROWS * DMODEL];
__device__ __align__(16) __half g_wh [E3 * DMODEL];

// Attention operands: Q hi/lo fp16 (rope + 0.125*log2e scale), K single fp16 (rope),
// V single fp16 transposed [b][h][d][l].
#define QKV_ELEMS (BATCH * NHEADS * L_SEQ * DK)
__device__ __align__(16) __half g_qhi[QKV_ELEMS];
__device__ __align__(16) __half g_qlo[QKV_ELEMS];
__device__ __align__(16) __half g_kh [QKV_ELEMS];
__device__ __align__(16) __half g_vh [QKV_ELEMS];

__constant__ float c_theta[16] = {
    1.0f,                     0.5623413251903491f,     0.31622776601683794f,   0.17782794100389228f,
    0.1f,                     0.05623413251903491f,    0.031622776601683794f,  0.017782794100389228f,
    0.01f,                    0.005623413251903491f,   0.0031622776601683794f, 0.0017782794100389228f,
    0.001f,                   0.0005623413251903491f,  0.00031622776601683794f,0.00017782794100389227f
};

// ---------------------------------------------------------------------------
// Helpers
// ---------------------------------------------------------------------------
#define MMA_F16(C, A, B)                                                         \
    asm volatile("mma.sync.aligned.m16n8k16.row.col.f32.f16.f16.f32 "            \
                 "{%0,%1,%2,%3}, {%4,%5,%6,%7}, {%8,%9}, {%0,%1,%2,%3};"         \
                 : "+f"((C)[0]), "+f"((C)[1]), "+f"((C)[2]), "+f"((C)[3])        \
                 : "r"((A)[0]), "r"((A)[1]), "r"((A)[2]), "r"((A)[3]),           \
                   "r"((B)[0]), "r"((B)[1]))

__device__ __forceinline__ void ldm4(unsigned* r, unsigned a) {
    asm volatile("ldmatrix.sync.aligned.m8n8.x4.shared.b16 {%0,%1,%2,%3}, [%4];"
                 : "=r"(r[0]), "=r"(r[1]), "=r"(r[2]), "=r"(r[3]) : "r"(a));
}

__device__ __forceinline__ float ex2f(float x) {
    float r;
    asm("ex2.approx.ftz.f32 %0, %1;" : "=f"(r) : "f"(x));
    return r;
}

__device__ __forceinline__ void cp16(unsigned s, const void* g) {
    asm volatile("cp.async.ca.shared.global [%0], [%1], 16;" :: "r"(s), "l"(g));
}

__device__ __forceinline__ unsigned smem_u32(const void* p) {
    return (unsigned)__cvta_generic_to_shared(p);
}

// fp32 pair -> fp16 hi pair + fp16 residual pair (packed as u32 each)
__device__ __forceinline__ void pack_hilo_h(float f0, float f1, unsigned& h, unsigned& l) {
    __half2 hb = __floats2half2_rn(f0, f1);
    float2 fb = __half22float2(hb);
    __half2 lb = __floats2half2_rn(f0 - fb.x, f1 - fb.y);
    h = *reinterpret_cast<unsigned*>(&hb);
    l = *reinterpret_cast<unsigned*>(&lb);
}

// ---------------------------------------------------------------------------
// Split kernels
// ---------------------------------------------------------------------------
__global__ void __launch_bounds__(256) split_x(const float* __restrict__ src) {
    int t = blockIdx.x * 256 + threadIdx.x;
    float4 v = reinterpret_cast<const float4*>(src)[t];
    unsigned hp[2], lp[2];
    pack_hilo_h(v.x, v.y, hp[0], lp[0]);
    pack_hilo_h(v.z, v.w, hp[1], lp[1]);
    reinterpret_cast<uint2*>(g_xhi)[t] = make_uint2(hp[0], hp[1]);
    reinterpret_cast<uint2*>(g_xlo)[t] = make_uint2(lp[0], lp[1]);
}
__global__ void __launch_bounds__(256) split_w(const float* __restrict__ src) {
    int t = blockIdx.x * 256 + threadIdx.x;
    float4 v = reinterpret_cast<const float4*>(src)[t];
    __half2 h0 = __floats2half2_rn(v.x, v.y);
    __half2 h1 = __floats2half2_rn(v.z, v.w);
    reinterpret_cast<uint2*>(g_wh)[t] =
        make_uint2(*reinterpret_cast<unsigned*>(&h0), *reinterpret_cast<unsigned*>(&h1));
}

// ---------------------------------------------------------------------------
// Kernel 1: QKV projection GEMM (fp16x2 mma.sync + ldmatrix + cp.async).
// CTA tile 128x128, BK=32, 8 warps, warp tile 32x64, 2-stage double buffer.
// acc = Xhi*Wh + Xlo*Wh. smem/stage: {Ahi, Alo, Bh} x 128x40 fp16 = 30KB.
// ---------------------------------------------------------------------------
#define KPAD 40
#define ARR_B  (128 * KPAD * 2)
#define STG_B  (3 * ARR_B)
#define QKV_SMEM (2 * STG_B)

#define G_ISSUE(KT, ST)                                                               \
    do {                                                                              \
        const int _k0 = (KT) * 32;                                                    \
        _Pragma("unroll")                                                             \
        for (int _arr = 0; _arr < 3; _arr++) {                                        \
            _Pragma("unroll")                                                         \
            for (int _rep = 0; _rep < 2; _rep++) {                                    \
                int _sub = _rep * 256 + tid;                                          \
                int _row = _sub >> 2;                                                 \
                int _ch  = _sub & 3;                                                  \
                unsigned _sp = smem0 + (ST) * STG_B + _arr * ARR_B + _row * (KPAD*2) + _ch * 16; \
                const __half* _gp;                                                    \
                if      (_arr == 0) _gp = g_xhi + (size_t)(r0 + _row) * DMODEL + _k0 + _ch * 8; \
                else if (_arr == 1) _gp = g_xlo + (size_t)(r0 + _row) * DMODEL + _k0 + _ch * 8; \
                else                _gp = g_wh  + (size_t)(e0 + _row) * DMODEL + _k0 + _ch * 8; \
                cp16(_sp, _gp);                                                       \
            }                                                                         \
        }                                                                             \
        asm volatile("cp.async.commit_group;");                                       \
    } while (0)

__global__ void __launch_bounds__(256) qkv_gemm_tc() {
    extern __shared__ __align__(16) char qsm[];
    const unsigned smem0 = smem_u32(qsm);

    const int tid   = threadIdx.x;
    const int wid   = tid >> 5;
    const int lane  = tid & 31;
    const int warpM = wid >> 1;
    const int warpN = wid & 1;
    const int r0    = blockIdx.y * 128;
    const int e0    = blockIdx.x * 128;

    const int fr = lane >> 2;
    const int fc = (lane & 3) * 2;

    const int lrA = lane & 15;
    const int lcA = (lane >> 4) << 3;
    const int lrB = (lane & 7) + ((lane >> 4) << 3);
    const int lcB = ((lane >> 3) & 1) << 3;

    float acc[2][8][4] = {};

    G_ISSUE(0, 0);
    G_ISSUE(1, 1);

    for (int kt = 0; kt < 32; kt++) {
        if (kt < 31) asm volatile("cp.async.wait_group 1;");
        else         asm volatile("cp.async.wait_group 0;");
        __syncthreads();

        const unsigned uA_hi = smem0 + (kt & 1) * STG_B;
        const unsigned uA_lo = uA_hi + ARR_B;
        const unsigned uB    = uA_hi + 2 * ARR_B;

#pragma unroll
        for (int ks = 0; ks < 32; ks += 16) {
            unsigned ahi[2][4], alo[2][4], bh[4][4];
#pragma unroll
            for (int mf = 0; mf < 2; mf++) {
                const unsigned ao = (unsigned)(((warpM * 32 + mf * 16 + lrA) * KPAD + ks + lcA) * 2);
                ldm4(ahi[mf], uA_hi + ao);
                ldm4(alo[mf], uA_lo + ao);
            }
#pragma unroll
            for (int g4 = 0; g4 < 4; g4++) {
                const unsigned bo = (unsigned)(((warpN * 64 + g4 * 16 + lrB) * KPAD + ks + lcB) * 2);
                ldm4(bh[g4], uB + bo);
            }
#pragma unroll
            for (int mf = 0; mf < 2; mf++)
#pragma unroll
                for (int nf = 0; nf < 8; nf++) {
                    const unsigned* bf = &bh[nf >> 1][(nf & 1) * 2];
                    MMA_F16(acc[mf][nf], ahi[mf], bf);
                    MMA_F16(acc[mf][nf], alo[mf], bf);
                }
        }
        __syncthreads();
        if (kt + 2 < 32) G_ISSUE(kt + 2, kt & 1);
    }

#pragma unroll
    for (int mf = 0; mf < 2; mf++)
#pragma unroll
        for (int nf = 0; nf < 8; nf++) {
            const int row = r0 + warpM * 32 + mf * 16 + fr;
            const int col = e0 + warpN * 64 + nf * 8 + fc;
            *reinterpret_cast<float2*>(&g_qkv[(size_t)row * E3 + col]) =
                make_float2(acc[mf][nf][0], acc[mf][nf][1]);
            *reinterpret_cast<float2*>(&g_qkv[(size_t)(row + 8) * E3 + col]) =
                make_float2(acc[mf][nf][2], acc[mf][nf][3]);
        }
}

// ---------------------------------------------------------------------------
// Kernel 2: rope + convert. Q -> fp16 hi/lo (scaled), K -> single fp16.
// ---------------------------------------------------------------------------
#define QSCALE 0.1803368801111243f   // 0.125 * log2(e)

__global__ void __launch_bounds__(256) prep_qk() {
    const int t   = blockIdx.x * 256 + threadIdx.x;
    const int j   = t & 15;
    const int sqk = (t >> 4) & 1;
    const int h   = (t >> 5) & 15;
    const int r   = t >> 9;
    const int l   = r >> 1;
    const int b   = r & 1;

    const float* base = g_qkv + (size_t)r * E3 + h * 192 + sqk * 64;
    float x0 = base[j];
    float x1 = base[j + 16];
    float p0 = base[j + 32];
    float p1 = base[j + 48];

    float ang = (float)l * c_theta[j];
    float sn, cs;
    sincosf(ang, &sn, &cs);
    float y0 = x0 * cs - x1 * sn;
    float y1 = x1 * cs + x0 * sn;

    const size_t dst = ((size_t)(b * NHEADS + h) * L_SEQ + l) * DK;
    float vals[4] = {y0, y1, p0, p1};
    int   ds[4]   = {j, j + 16, j + 32, j + 48};

    if (sqk == 0) {
#pragma unroll
        for (int i = 0; i < 4; i++) {
            float v = vals[i] * QSCALE;
            __half hi = __float2half_rn(v);
            g_qhi[dst + ds[i]] = hi;
            g_qlo[dst + ds[i]] = __float2half_rn(v - __half2float(hi));
        }
    } else {
#pragma unroll
        for (int i = 0; i < 4; i++)
            g_kh[dst + ds[i]] = __float2half_rn(vals[i]);
    }
}

// ---------------------------------------------------------------------------
// Kernel 3: V transpose + convert -> single fp16, layout [b][h][d][l].
// ---------------------------------------------------------------------------
__global__ void __launch_bounds__(128) prep_v() {
    __shared__ float s[64][68];
    const int tile = blockIdx.x, h = blockIdx.y, b = blockIdx.z;
    const int tid = threadIdx.x;

#pragma unroll
    for (int i = 0; i < 8; i++) {
        int id  = i * 128 + tid;
        int row = id >> 4;
        int c4  = id & 15;
        const float* g = g_qkv + (size_t)((tile * 64 + row) * 2 + b) * E3 + h * 192 + 128 + c4 * 4;
        float4 v = *reinterpret_cast<const float4*>(g);
        s[row][c4 * 4 + 0] = v.x; s[row][c4 * 4 + 1] = v.y;
        s[row][c4 * 4 + 2] = v.z; s[row][c4 * 4 + 3] = v.w;
    }
    __syncthreads();

    const int d = tid & 63, part = tid >> 6;
    const size_t ob = ((size_t)(b * NHEADS + h) * DK + d) * L_SEQ + tile * 64 + part * 32;

#pragma unroll
    for (int kc = 0; kc < 4; kc++) {
        unsigned hw[4];
#pragma unroll
        for (int p = 0; p < 4; p++) {
            __half2 t = __floats2half2_rn(s[part * 32 + kc * 8 + p * 2 + 0][d],
                                          s[part * 32 + kc * 8 + p * 2 + 1][d]);
            hw[p] = *reinterpret_cast<unsigned*>(&t);
        }
        *reinterpret_cast<uint4*>(g_vh + ob + kc * 8) = make_uint4(hw[0], hw[1], hw[2], hw[3]);
    }
}

// ---------------------------------------------------------------------------
// Kernel 4: fp16x2 tensor-core flash attention.
// CTA = 128 queries x (h,b). 4 warps x 32 rows. KV tiles of 64, double-buffered.
// S = (Qhi + Qlo) Kh^T ; O += (Phi + Plo) Vh.
// smem (fp16 elems): Qhi 128x72 @0, Qlo @9216, stage s: {Kh 64x72, Vh 64x72} @18432+s*9216.
// Total 73,728 B -> 2 CTAs/SM.
// ---------------------------------------------------------------------------
#define ATTN_SMEM_BYTES ((18432 + 2 * 9216) * 2)   // 73728

__global__ void __launch_bounds__(128, 2) attn_tc(float* __restrict__ out) {
    extern __shared__ __align__(16) __half sm[];
    const unsigned smem_base = smem_u32(sm);

    const int tid  = threadIdx.x;
    const int w    = tid >> 5;
    const int lane = tid & 31;
    const int g    = lane >> 2;
    const int tg   = lane & 3;

    const int lrA = lane & 15;
    const int lcA = (lane >> 4) << 3;
    const int lrB = (lane & 7) + ((lane >> 4) << 3);
    const int lcB = ((lane >> 3) & 1) << 3;

    const int q0 = blockIdx.x * 128;
    const int h  = blockIdx.y;
    const int b  = blockIdx.z;
    const int hb = b * NHEADS + h;

    const size_t qkbase = (size_t)hb * L_SEQ * DK;
    const size_t vbase  = (size_t)hb * DK * L_SEQ;

    // Q tile loads (hi 8 iters + lo 8 iters)
#pragma unroll
    for (int i = 0; i < 16; i++) {
        int id  = i * 128 + tid;
        int rid = (id >> 3) & 127;
        int ch  = id & 7;
        const __half* gp = (i < 8 ? g_qhi : g_qlo) + qkbase + (size_t)(q0 + rid) * DK + ch * 8;
        unsigned sp = smem_base + ((i < 8 ? 0 : 9216) + rid * 72 + ch * 8) * 2;
        cp16(sp, gp);
    }

#define ISSUE_TILE(T, BUF)                                                            \
    do {                                                                              \
        _Pragma("unroll")                                                             \
        for (int i = 0; i < 8; i++) {                                                 \
            int id  = i * 128 + tid;                                                  \
            int arr = i >> 2;                                                         \
            int rid = (id >> 3) & 63;                                                 \
            int ch  = id & 7;                                                         \
            const __half* gp;                                                         \
            if (arr == 0) gp = g_kh + qkbase + (size_t)((T) * 64 + rid) * DK + ch * 8; \
            else          gp = g_vh + vbase + (size_t)rid * L_SEQ + (T) * 64 + ch * 8; \
            unsigned sp = smem_base + (18432 + (BUF) * 9216 + arr * 4608 + rid * 72 + ch * 8) * 2; \
            cp16(sp, gp);                                                             \
        }                                                                             \
    } while (0)

    ISSUE_TILE(0, 0);
    asm volatile("cp.async.commit_group;");

    float o[2][8][4] = {};
    float mrow[2][2] = {{-1e30f, -1e30f}, {-1e30f, -1e30f}};
    float lrow[2][2] = {};

    const int rb0 = w * 32;

    for (int t = 0; t < 32; t++) {
        const int cur = t & 1;
        if (t < 31) {
            ISSUE_TILE(t + 1, cur ^ 1);
            asm volatile("cp.async.commit_group;");
            asm volatile("cp.async.wait_group 1;");
        } else {
            asm volatile("cp.async.wait_group 0;");
        }
        __syncthreads();

        const unsigned uQh = smem_base;
        const unsigned uQl = smem_base + 9216 * 2;
        const unsigned uKh = smem_base + (18432 + cur * 9216) * 2;
        const unsigned uVh = uKh + 4608 * 2;

        // ---- S = (Qhi + Qlo) Kh^T ----
        float s[2][8][4] = {};
#pragma unroll
        for (int kf = 0; kf < 4; kf++) {
            unsigned ah[2][4], al[2][4], kh[4][4];
#pragma unroll
            for (int mf = 0; mf < 2; mf++) {
                const unsigned ao = (unsigned)(((rb0 + mf * 16 + lrA) * 72 + kf * 16 + lcA) * 2);
                ldm4(ah[mf], uQh + ao);
                ldm4(al[mf], uQl + ao);
            }
#pragma unroll
            for (int g4 = 0; g4 < 4; g4++) {
                const unsigned bo = (unsigned)(((g4 * 16 + lrB) * 72 + kf * 16 + lcB) * 2);
                ldm4(kh[g4], uKh + bo);
            }
#pragma unroll
            for (int nf = 0; nf < 8; nf++) {
                const unsigned* bf = &kh[nf >> 1][(nf & 1) * 2];
#pragma unroll
                for (int mf = 0; mf < 2; mf++) {
                    MMA_F16(s[mf][nf], ah[mf], bf);
                    MMA_F16(s[mf][nf], al[mf], bf);
                }
            }
        }

        // ---- online softmax (log2 domain) ----
        unsigned ph[2][4][4], pl[2][4][4];
#pragma unroll
        for (int mf = 0; mf < 2; mf++) {
            float mx0 = -1e30f, mx1 = -1e30f;
#pragma unroll
            for (int nf = 0; nf < 8; nf++) {
                mx0 = fmaxf(mx0, fmaxf(s[mf][nf][0], s[mf][nf][1]));
                mx1 = fmaxf(mx1, fmaxf(s[mf][nf][2], s[mf][nf][3]));
            }
            mx0 = fmaxf(mx0, __shfl_xor_sync(0xffffffffu, mx0, 1));
            mx0 = fmaxf(mx0, __shfl_xor_sync(0xffffffffu, mx0, 2));
            mx1 = fmaxf(mx1, __shfl_xor_sync(0xffffffffu, mx1, 1));
            mx1 = fmaxf(mx1, __shfl_xor_sync(0xffffffffu, mx1, 2));

            float mn0 = fmaxf(mrow[mf][0], mx0);
            float mn1 = fmaxf(mrow[mf][1], mx1);
            float sc0 = ex2f(mrow[mf][0] - mn0);
            float sc1 = ex2f(mrow[mf][1] - mn1);
            mrow[mf][0] = mn0;
            mrow[mf][1] = mn1;

            float rs0 = 0.f, rs1 = 0.f;
#pragma unroll
            for (int nf = 0; nf < 8; nf++) {
                s[mf][nf][0] = ex2f(s[mf][nf][0] - mn0);
                s[mf][nf][1] = ex2f(s[mf][nf][1] - mn0);
                s[mf][nf][2] = ex2f(s[mf][nf][2] - mn1);
                s[mf][nf][3] = ex2f(s[mf][nf][3] - mn1);
                rs0 += s[mf][nf][0] + s[mf][nf][1];
                rs1 += s[mf][nf][2] + s[mf][nf][3];
            }
            rs0 += __shfl_xor_sync(0xffffffffu, rs0, 1);
            rs0 += __shfl_xor_sync(0xffffffffu, rs0, 2);
            rs1 += __shfl_xor_sync(0xffffffffu, rs1, 1);
            rs1 += __shfl_xor_sync(0xffffffffu, rs1, 2);
            lrow[mf][0] = lrow[mf][0] * sc0 + rs0;
            lrow[mf][1] = lrow[mf][1] * sc1 + rs1;

#pragma unroll
            for (int nf = 0; nf < 8; nf++) {
                o[mf][nf][0] *= sc0; o[mf][nf][1] *= sc0;
                o[mf][nf][2] *= sc1; o[mf][nf][3] *= sc1;
            }

#pragma unroll
            for (int kf = 0; kf < 4; kf++) {
                const int n0 = 2 * kf, n1 = 2 * kf + 1;
                pack_hilo_h(s[mf][n0][0], s[mf][n0][1], ph[mf][kf][0], pl[mf][kf][0]);
                pack_hilo_h(s[mf][n0][2], s[mf][n0][3], ph[mf][kf][1], pl[mf][kf][1]);
                pack_hilo_h(s[mf][n1][0], s[mf][n1][1], ph[mf][kf][2], pl[mf][kf][2]);
                pack_hilo_h(s[mf][n1][2], s[mf][n1][3], ph[mf][kf][3], pl[mf][kf][3]);
            }
        }

        // ---- O += (Phi + Plo) Vh ----
#pragma unroll
        for (int kf = 0; kf < 4; kf++) {
            unsigned vh[4][4];
#pragma unroll
            for (int g4 = 0; g4 < 4; g4++) {
                const unsigned bo = (unsigned)(((g4 * 16 + lrB) * 72 + kf * 16 + lcB) * 2);
                ldm4(vh[g4], uVh + bo);
            }
#pragma unroll
            for (int nf = 0; nf < 8; nf++) {
                const unsigned* bf = &vh[nf >> 1][(nf & 1) * 2];
#pragma unroll
                for (int mf = 0; mf < 2; mf++) {
                    MMA_F16(o[mf][nf], ph[mf][kf], bf);
                    MMA_F16(o[mf][nf], pl[mf][kf], bf);
                }
            }
        }
        __syncthreads();
    }

    // ---- epilogue: out[l][b][h*64 + d] ----
#pragma unroll
    for (int mf = 0; mf < 2; mf++) {
        const float inv0 = 1.0f / lrow[mf][0];
        const float inv1 = 1.0f / lrow[mf][1];
        const int r0 = q0 + rb0 + mf * 16 + g;
#pragma unroll
        for (int nf = 0; nf < 8; nf++) {
            const int col = h * 64 + nf * 8 + tg * 2;
            *reinterpret_cast<float2*>(out + (size_t)(r0 * 2 + b) * DMODEL + col) =
                make_float2(o[mf][nf][0] * inv0, o[mf][nf][1] * inv0);
            *reinterpret_cast<float2*>(out + (size_t)((r0 + 8) * 2 + b) * DMODEL + col) =
                make_float2(o[mf][nf][2] * inv1, o[mf][nf][3] * inv1);
        }
    }
}

// ---------------------------------------------------------------------------
extern "C" void kernel_launch(void* const* d_in, const int* in_sizes, int n_in,
                              void* d_out, int out_size) {
    const float* x = (const float*)d_in[0];
    const float* w = (const float*)d_in[1];
    if (n_in >= 2 && in_sizes[0] == E3 * DMODEL && in_sizes[1] == NROWS * DMODEL) {
        const float* t = x; x = w; w = t;
    }
    float* out = (float*)d_out;

    static bool attr_set = false;
    if (!attr_set) {
        cudaFuncSetAttribute(attn_tc, cudaFuncAttributeMaxDynamicSharedMemorySize,
                             ATTN_SMEM_BYTES);
        cudaFuncSetAttribute(qkv_gemm_tc, cudaFuncAttributeMaxDynamicSharedMemorySize,
                             QKV_SMEM);
        attr_set = true;
    }

    split_x<<<(NROWS * DMODEL / 4) / 256, 256>>>(x);
    split_w<<<(E3 * DMODEL / 4) / 256, 256>>>(w);
    qkv_gemm_tc<<<dim3(E3 / 128, NROWS / 128), 256, QKV_SMEM>>>();
    prep_qk<<<(NROWS * NHEADS * 2 * 16) / 256, 256>>>();
    prep_v<<<dim3(L_SEQ / 64, NHEADS, BATCH), 128>>>();
    attn_tc<<<dim3(L_SEQ / 128, NHEADS, BATCH), 128, ATTN_SMEM_BYTES>>>(out);
}

// round 11
// speedup vs baseline: 2.1043x; 1.4077x over previous
#include <cuda_runtime.h>
#include <cuda_fp16.h>

#define L_SEQ  2048
#define BATCH  2
#define DMODEL 1024
#define NHEADS 16
#define DK     64
#define E3     3072
#define NROWS  4096

// fp32 QKV projection scratch: [NROWS][E3], row r = l*BATCH + b, col e = h*192 + {q,k,v}
__device__ float g_qkv[NROWS * E3];

// fp16 operands for the projection GEMM (single precision level each side)
__device__ __align__(16) __half g_xh[NROWS * DMODEL];
__device__ __align__(16) __half g_wh[E3 * DMODEL];

// Attention operands: Q hi/lo fp16 (rope + 0.125*log2e scale; scores need absolute
// precision for exp2), K single fp16 (rope), V single fp16 transposed [b][h][d][l].
#define QKV_ELEMS (BATCH * NHEADS * L_SEQ * DK)
__device__ __align__(16) __half g_qhi[QKV_ELEMS];
__device__ __align__(16) __half g_qlo[QKV_ELEMS];
__device__ __align__(16) __half g_kh [QKV_ELEMS];
__device__ __align__(16) __half g_vh [QKV_ELEMS];

__constant__ float c_theta[16] = {
    1.0f,                     0.5623413251903491f,     0.31622776601683794f,   0.17782794100389228f,
    0.1f,                     0.05623413251903491f,    0.031622776601683794f,  0.017782794100389228f,
    0.01f,                    0.005623413251903491f,   0.0031622776601683794f, 0.0017782794100389228f,
    0.001f,                   0.0005623413251903491f,  0.00031622776601683794f,0.00017782794100389227f
};

// ---------------------------------------------------------------------------
// Helpers
// ---------------------------------------------------------------------------
#define MMA_F16(C, A, B)                                                         \
    asm volatile("mma.sync.aligned.m16n8k16.row.col.f32.f16.f16.f32 "            \
                 "{%0,%1,%2,%3}, {%4,%5,%6,%7}, {%8,%9}, {%0,%1,%2,%3};"         \
                 : "+f"((C)[0]), "+f"((C)[1]), "+f"((C)[2]), "+f"((C)[3])        \
                 : "r"((A)[0]), "r"((A)[1]), "r"((A)[2]), "r"((A)[3]),           \
                   "r"((B)[0]), "r"((B)[1]))

__device__ __forceinline__ void ldm4(unsigned* r, unsigned a) {
    asm volatile("ldmatrix.sync.aligned.m8n8.x4.shared.b16 {%0,%1,%2,%3}, [%4];"
                 : "=r"(r[0]), "=r"(r[1]), "=r"(r[2]), "=r"(r[3]) : "r"(a));
}

__device__ __forceinline__ float ex2f(float x) {
    float r;
    asm("ex2.approx.ftz.f32 %0, %1;" : "=f"(r) : "f"(x));
    return r;
}

__device__ __forceinline__ void cp16(unsigned s, const void* g) {
    asm volatile("cp.async.ca.shared.global [%0], [%1], 16;" :: "r"(s), "l"(g));
}

__device__ __forceinline__ unsigned smem_u32(const void* p) {
    return (unsigned)__cvta_generic_to_shared(p);
}

__device__ __forceinline__ unsigned pack_h2(float f0, float f1) {
    __half2 h = __floats2half2_rn(f0, f1);
    return *reinterpret_cast<unsigned*>(&h);
}

// ---------------------------------------------------------------------------
// Fused convert kernel: X -> g_xh, W -> g_wh (single fp16 each).
// ---------------------------------------------------------------------------
#define NX4 (NROWS * DMODEL / 4)
#define NW4 (E3 * DMODEL / 4)

__global__ void __launch_bounds__(256) convert_xw(const float* __restrict__ x,
                                                  const float* __restrict__ w) {
    int t = blockIdx.x * 256 + threadIdx.x;
    const float4 v = (t < NX4) ? reinterpret_cast<const float4*>(x)[t]
                               : reinterpret_cast<const float4*>(w)[t - NX4];
    uint2 o = make_uint2(pack_h2(v.x, v.y), pack_h2(v.z, v.w));
    if (t < NX4) reinterpret_cast<uint2*>(g_xh)[t] = o;
    else         reinterpret_cast<uint2*>(g_wh)[t - NX4] = o;
}

// ---------------------------------------------------------------------------
// Kernel 1: QKV projection GEMM (fp16 single x single, mma.sync + ldmatrix).
// CTA tile 128x128, BK=32, 8 warps, warp tile 32x64, 3-stage cp.async pipeline.
// smem/stage: {Ah, Bh} x 128x40 fp16 = 20KB.
// ---------------------------------------------------------------------------
#define KPAD 40
#define ARR_B  (128 * KPAD * 2)
#define STG_B  (2 * ARR_B)
#define QKV_SMEM (3 * STG_B)

#define G_ISSUE(KT, ST)                                                               \
    do {                                                                              \
        const int _k0 = (KT) * 32;                                                    \
        _Pragma("unroll")                                                             \
        for (int _arr = 0; _arr < 2; _arr++) {                                        \
            _Pragma("unroll")                                                         \
            for (int _rep = 0; _rep < 2; _rep++) {                                    \
                int _sub = _rep * 256 + tid;                                          \
                int _row = _sub >> 2;                                                 \
                int _ch  = _sub & 3;                                                  \
                unsigned _sp = smem0 + (ST) * STG_B + _arr * ARR_B + _row * (KPAD*2) + _ch * 16; \
                const __half* _gp;                                                    \
                if (_arr == 0) _gp = g_xh + (size_t)(r0 + _row) * DMODEL + _k0 + _ch * 8; \
                else           _gp = g_wh + (size_t)(e0 + _row) * DMODEL + _k0 + _ch * 8; \
                cp16(_sp, _gp);                                                       \
            }                                                                         \
        }                                                                             \
        asm volatile("cp.async.commit_group;");                                       \
    } while (0)

__global__ void __launch_bounds__(256) qkv_gemm_tc() {
    extern __shared__ __align__(16) char qsm[];
    const unsigned smem0 = smem_u32(qsm);

    const int tid   = threadIdx.x;
    const int wid   = tid >> 5;
    const int lane  = tid & 31;
    const int warpM = wid >> 1;
    const int warpN = wid & 1;
    const int r0    = blockIdx.y * 128;
    const int e0    = blockIdx.x * 128;

    const int fr = lane >> 2;
    const int fc = (lane & 3) * 2;

    const int lrA = lane & 15;
    const int lcA = (lane >> 4) << 3;
    const int lrB = (lane & 7) + ((lane >> 4) << 3);
    const int lcB = ((lane >> 3) & 1) << 3;

    float acc[2][8][4] = {};

    G_ISSUE(0, 0);
    G_ISSUE(1, 1);
    G_ISSUE(2, 2);

    for (int kt = 0; kt < 32; kt++) {
        if (kt < 30)       asm volatile("cp.async.wait_group 2;");
        else if (kt == 30) asm volatile("cp.async.wait_group 1;");
        else               asm volatile("cp.async.wait_group 0;");
        __syncthreads();

        const int st = kt % 3;
        const unsigned uA = smem0 + st * STG_B;
        const unsigned uB = uA + ARR_B;

#pragma unroll
        for (int ks = 0; ks < 32; ks += 16) {
            unsigned ah[2][4], bh[4][4];
#pragma unroll
            for (int mf = 0; mf < 2; mf++) {
                const unsigned ao = (unsigned)(((warpM * 32 + mf * 16 + lrA) * KPAD + ks + lcA) * 2);
                ldm4(ah[mf], uA + ao);
            }
#pragma unroll
            for (int g4 = 0; g4 < 4; g4++) {
                const unsigned bo = (unsigned)(((warpN * 64 + g4 * 16 + lrB) * KPAD + ks + lcB) * 2);
                ldm4(bh[g4], uB + bo);
            }
#pragma unroll
            for (int mf = 0; mf < 2; mf++)
#pragma unroll
                for (int nf = 0; nf < 8; nf++) {
                    const unsigned* bf = &bh[nf >> 1][(nf & 1) * 2];
                    MMA_F16(acc[mf][nf], ah[mf], bf);
                }
        }
        __syncthreads();
        if (kt + 3 < 32) G_ISSUE(kt + 3, st);
    }

#pragma unroll
    for (int mf = 0; mf < 2; mf++)
#pragma unroll
        for (int nf = 0; nf < 8; nf++) {
            const int row = r0 + warpM * 32 + mf * 16 + fr;
            const int col = e0 + warpN * 64 + nf * 8 + fc;
            *reinterpret_cast<float2*>(&g_qkv[(size_t)row * E3 + col]) =
                make_float2(acc[mf][nf][0], acc[mf][nf][1]);
            *reinterpret_cast<float2*>(&g_qkv[(size_t)(row + 8) * E3 + col]) =
                make_float2(acc[mf][nf][2], acc[mf][nf][3]);
        }
}

// ---------------------------------------------------------------------------
// Kernel 2: rope + convert. Q -> fp16 hi/lo (scaled), K -> single fp16.
// ---------------------------------------------------------------------------
#define QSCALE 0.1803368801111243f   // 0.125 * log2(e)

__global__ void __launch_bounds__(256) prep_qk() {
    const int t   = blockIdx.x * 256 + threadIdx.x;
    const int j   = t & 15;
    const int sqk = (t >> 4) & 1;
    const int h   = (t >> 5) & 15;
    const int r   = t >> 9;
    const int l   = r >> 1;
    const int b   = r & 1;

    const float* base = g_qkv + (size_t)r * E3 + h * 192 + sqk * 64;
    float x0 = base[j];
    float x1 = base[j + 16];
    float p0 = base[j + 32];
    float p1 = base[j + 48];

    float ang = (float)l * c_theta[j];
    float sn, cs;
    sincosf(ang, &sn, &cs);
    float y0 = x0 * cs - x1 * sn;
    float y1 = x1 * cs + x0 * sn;

    const size_t dst = ((size_t)(b * NHEADS + h) * L_SEQ + l) * DK;
    float vals[4] = {y0, y1, p0, p1};
    int   ds[4]   = {j, j + 16, j + 32, j + 48};

    if (sqk == 0) {
#pragma unroll
        for (int i = 0; i < 4; i++) {
            float v = vals[i] * QSCALE;
            __half hi = __float2half_rn(v);
            g_qhi[dst + ds[i]] = hi;
            g_qlo[dst + ds[i]] = __float2half_rn(v - __half2float(hi));
        }
    } else {
#pragma unroll
        for (int i = 0; i < 4; i++)
            g_kh[dst + ds[i]] = __float2half_rn(vals[i]);
    }
}

// ---------------------------------------------------------------------------
// Kernel 3: V transpose + convert -> single fp16, layout [b][h][d][l].
// ---------------------------------------------------------------------------
__global__ void __launch_bounds__(128) prep_v() {
    __shared__ float s[64][68];
    const int tile = blockIdx.x, h = blockIdx.y, b = blockIdx.z;
    const int tid = threadIdx.x;

#pragma unroll
    for (int i = 0; i < 8; i++) {
        int id  = i * 128 + tid;
        int row = id >> 4;
        int c4  = id & 15;
        const float* g = g_qkv + (size_t)((tile * 64 + row) * 2 + b) * E3 + h * 192 + 128 + c4 * 4;
        float4 v = *reinterpret_cast<const float4*>(g);
        s[row][c4 * 4 + 0] = v.x; s[row][c4 * 4 + 1] = v.y;
        s[row][c4 * 4 + 2] = v.z; s[row][c4 * 4 + 3] = v.w;
    }
    __syncthreads();

    const int d = tid & 63, part = tid >> 6;
    const size_t ob = ((size_t)(b * NHEADS + h) * DK + d) * L_SEQ + tile * 64 + part * 32;

#pragma unroll
    for (int kc = 0; kc < 4; kc++) {
        unsigned hw[4];
#pragma unroll
        for (int p = 0; p < 4; p++)
            hw[p] = pack_h2(s[part * 32 + kc * 8 + p * 2 + 0][d],
                            s[part * 32 + kc * 8 + p * 2 + 1][d]);
        *reinterpret_cast<uint4*>(g_vh + ob + kc * 8) = make_uint4(hw[0], hw[1], hw[2], hw[3]);
    }
}

// ---------------------------------------------------------------------------
// Kernel 4: fp16 tensor-core flash attention.
// S = (Qhi + Qlo) Kh^T (2 MMAs) ; O += Ph Vh (1 MMA).
// CTA = 128 queries x (h,b). 4 warps x 32 rows. KV tiles of 64, double-buffered.
// smem 73,728 B -> 2 CTAs/SM.
// ---------------------------------------------------------------------------
#define ATTN_SMEM_BYTES ((18432 + 2 * 9216) * 2)   // 73728

__global__ void __launch_bounds__(128, 2) attn_tc(float* __restrict__ out) {
    extern __shared__ __align__(16) __half sm[];
    const unsigned smem_base = smem_u32(sm);

    const int tid  = threadIdx.x;
    const int w    = tid >> 5;
    const int lane = tid & 31;
    const int g    = lane >> 2;
    const int tg   = lane & 3;

    const int lrA = lane & 15;
    const int lcA = (lane >> 4) << 3;
    const int lrB = (lane & 7) + ((lane >> 4) << 3);
    const int lcB = ((lane >> 3) & 1) << 3;

    const int q0 = blockIdx.x * 128;
    const int h  = blockIdx.y;
    const int b  = blockIdx.z;
    const int hb = b * NHEADS + h;

    const size_t qkbase = (size_t)hb * L_SEQ * DK;
    const size_t vbase  = (size_t)hb * DK * L_SEQ;

#pragma unroll
    for (int i = 0; i < 16; i++) {
        int id  = i * 128 + tid;
        int rid = (id >> 3) & 127;
        int ch  = id & 7;
        const __half* gp = (i < 8 ? g_qhi : g_qlo) + qkbase + (size_t)(q0 + rid) * DK + ch * 8;
        unsigned sp = smem_base + ((i < 8 ? 0 : 9216) + rid * 72 + ch * 8) * 2;
        cp16(sp, gp);
    }

#define ISSUE_TILE(T, BUF)                                                            \
    do {                                                                              \
        _Pragma("unroll")                                                             \
        for (int i = 0; i < 8; i++) {                                                 \
            int id  = i * 128 + tid;                                                  \
            int arr = i >> 2;                                                         \
            int rid = (id >> 3) & 63;                                                 \
            int ch  = id & 7;                                                         \
            const __half* gp;                                                         \
            if (arr == 0) gp = g_kh + qkbase + (size_t)((T) * 64 + rid) * DK + ch * 8; \
            else          gp = g_vh + vbase + (size_t)rid * L_SEQ + (T) * 64 + ch * 8; \
            unsigned sp = smem_base + (18432 + (BUF) * 9216 + arr * 4608 + rid * 72 + ch * 8) * 2; \
            cp16(sp, gp);                                                             \
        }                                                                             \
    } while (0)

    ISSUE_TILE(0, 0);
    asm volatile("cp.async.commit_group;");

    float o[2][8][4] = {};
    float mrow[2][2] = {{-1e30f, -1e30f}, {-1e30f, -1e30f}};
    float lrow[2][2] = {};

    const int rb0 = w * 32;

    for (int t = 0; t < 32; t++) {
        const int cur = t & 1;
        if (t < 31) {
            ISSUE_TILE(t + 1, cur ^ 1);
            asm volatile("cp.async.commit_group;");
            asm volatile("cp.async.wait_group 1;");
        } else {
            asm volatile("cp.async.wait_group 0;");
        }
        __syncthreads();

        const unsigned uQh = smem_base;
        const unsigned uQl = smem_base + 9216 * 2;
        const unsigned uKh = smem_base + (18432 + cur * 9216) * 2;
        const unsigned uVh = uKh + 4608 * 2;

        // ---- S = (Qhi + Qlo) Kh^T ----
        float s[2][8][4] = {};
#pragma unroll
        for (int kf = 0; kf < 4; kf++) {
            unsigned ah[2][4], al[2][4], kh[4][4];
#pragma unroll
            for (int mf = 0; mf < 2; mf++) {
                const unsigned ao = (unsigned)(((rb0 + mf * 16 + lrA) * 72 + kf * 16 + lcA) * 2);
                ldm4(ah[mf], uQh + ao);
                ldm4(al[mf], uQl + ao);
            }
#pragma unroll
            for (int g4 = 0; g4 < 4; g4++) {
                const unsigned bo = (unsigned)(((g4 * 16 + lrB) * 72 + kf * 16 + lcB) * 2);
                ldm4(kh[g4], uKh + bo);
            }
#pragma unroll
            for (int nf = 0; nf < 8; nf++) {
                const unsigned* bf = &kh[nf >> 1][(nf & 1) * 2];
#pragma unroll
                for (int mf = 0; mf < 2; mf++) {
                    MMA_F16(s[mf][nf], ah[mf], bf);
                    MMA_F16(s[mf][nf], al[mf], bf);
                }
            }
        }

        // ---- online softmax (log2 domain) ----
        unsigned ph[2][4][4];
#pragma unroll
        for (int mf = 0; mf < 2; mf++) {
            float mx0 = -1e30f, mx1 = -1e30f;
#pragma unroll
            for (int nf = 0; nf < 8; nf++) {
                mx0 = fmaxf(mx0, fmaxf(s[mf][nf][0], s[mf][nf][1]));
                mx1 = fmaxf(mx1, fmaxf(s[mf][nf][2], s[mf][nf][3]));
            }
            mx0 = fmaxf(mx0, __shfl_xor_sync(0xffffffffu, mx0, 1));
            mx0 = fmaxf(mx0, __shfl_xor_sync(0xffffffffu, mx0, 2));
            mx1 = fmaxf(mx1, __shfl_xor_sync(0xffffffffu, mx1, 1));
            mx1 = fmaxf(mx1, __shfl_xor_sync(0xffffffffu, mx1, 2));

            float mn0 = fmaxf(mrow[mf][0], mx0);
            float mn1 = fmaxf(mrow[mf][1], mx1);
            float sc0 = ex2f(mrow[mf][0] - mn0);
            float sc1 = ex2f(mrow[mf][1] - mn1);
            mrow[mf][0] = mn0;
            mrow[mf][1] = mn1;

            float rs0 = 0.f, rs1 = 0.f;
#pragma unroll
            for (int nf = 0; nf < 8; nf++) {
                s[mf][nf][0] = ex2f(s[mf][nf][0] - mn0);
                s[mf][nf][1] = ex2f(s[mf][nf][1] - mn0);
                s[mf][nf][2] = ex2f(s[mf][nf][2] - mn1);
                s[mf][nf][3] = ex2f(s[mf][nf][3] - mn1);
                rs0 += s[mf][nf][0] + s[mf][nf][1];
                rs1 += s[mf][nf][2] + s[mf][nf][3];
            }
            rs0 += __shfl_xor_sync(0xffffffffu, rs0, 1);
            rs0 += __shfl_xor_sync(0xffffffffu, rs0, 2);
            rs1 += __shfl_xor_sync(0xffffffffu, rs1, 1);
            rs1 += __shfl_xor_sync(0xffffffffu, rs1, 2);
            lrow[mf][0] = lrow[mf][0] * sc0 + rs0;
            lrow[mf][1] = lrow[mf][1] * sc1 + rs1;

#pragma unroll
            for (int nf = 0; nf < 8; nf++) {
                o[mf][nf][0] *= sc0; o[mf][nf][1] *= sc0;
                o[mf][nf][2] *= sc1; o[mf][nf][3] *= sc1;
            }

            // pack P into single-fp16 A-fragments
#pragma unroll
            for (int kf = 0; kf < 4; kf++) {
                const int n0 = 2 * kf, n1 = 2 * kf + 1;
                ph[mf][kf][0] = pack_h2(s[mf][n0][0], s[mf][n0][1]);
                ph[mf][kf][1] = pack_h2(s[mf][n0][2], s[mf][n0][3]);
                ph[mf][kf][2] = pack_h2(s[mf][n1][0], s[mf][n1][1]);
                ph[mf][kf][3] = pack_h2(s[mf][n1][2], s[mf][n1][3]);
            }
        }

        // ---- O += Ph Vh ----
#pragma unroll
        for (int kf = 0; kf < 4; kf++) {
            unsigned vh[4][4];
#pragma unroll
            for (int g4 = 0; g4 < 4; g4++) {
                const unsigned bo = (unsigned)(((g4 * 16 + lrB) * 72 + kf * 16 + lcB) * 2);
                ldm4(vh[g4], uVh + bo);
            }
#pragma unroll
            for (int nf = 0; nf < 8; nf++) {
                const unsigned* bf = &vh[nf >> 1][(nf & 1) * 2];
#pragma unroll
                for (int mf = 0; mf < 2; mf++)
                    MMA_F16(o[mf][nf], ph[mf][kf], bf);
            }
        }
        __syncthreads();
    }

    // ---- epilogue: out[l][b][h*64 + d] ----
#pragma unroll
    for (int mf = 0; mf < 2; mf++) {
        const float inv0 = 1.0f / lrow[mf][0];
        const float inv1 = 1.0f / lrow[mf][1];
        const int r0 = q0 + rb0 + mf * 16 + g;
#pragma unroll
        for (int nf = 0; nf < 8; nf++) {
            const int col = h * 64 + nf * 8 + tg * 2;
            *reinterpret_cast<float2*>(out + (size_t)(r0 * 2 + b) * DMODEL + col) =
                make_float2(o[mf][nf][0] * inv0, o[mf][nf][1] * inv0);
            *reinterpret_cast<float2*>(out + (size_t)((r0 + 8) * 2 + b) * DMODEL + col) =
                make_float2(o[mf][nf][2] * inv1, o[mf][nf][3] * inv1);
        }
    }
}

// ---------------------------------------------------------------------------
extern "C" void kernel_launch(void* const* d_in, const int* in_sizes, int n_in,
                              void* d_out, int out_size) {
    const float* x = (const float*)d_in[0];
    const float* w = (const float*)d_in[1];
    if (n_in >= 2 && in_sizes[0] == E3 * DMODEL && in_sizes[1] == NROWS * DMODEL) {
        const float* t = x; x = w; w = t;
    }
    float* out = (float*)d_out;

    static bool attr_set = false;
    if (!attr_set) {
        cudaFuncSetAttribute(attn_tc, cudaFuncAttributeMaxDynamicSharedMemorySize,
                             ATTN_SMEM_BYTES);
        cudaFuncSetAttribute(qkv_gemm_tc, cudaFuncAttributeMaxDynamicSharedMemorySize,
                             QKV_SMEM);
        attr_set = true;
    }

    convert_xw<<<(NX4 + NW4) / 256, 256>>>(x, w);
    qkv_gemm_tc<<<dim3(E3 / 128, NROWS / 128), 256, QKV_SMEM>>>();
    prep_qk<<<(NROWS * NHEADS * 2 * 16) / 256, 256>>>();
    prep_v<<<dim3(L_SEQ / 64, NHEADS, BATCH), 128>>>();
    attn_tc<<<dim3(L_SEQ / 128, NHEADS, BATCH), 128, ATTN_SMEM_BYTES>>>(out);
}

// round 14
// speedup vs baseline: 2.1215x; 1.0082x over previous
#include <cuda_runtime.h>
#include <cuda_fp16.h>

#define L_SEQ  2048
#define BATCH  2
#define DMODEL 1024
#define NHEADS 16
#define DK     64
#define E3     3072
#define NROWS  4096

// fp32 QKV projection scratch: [NROWS][E3], row r = l*BATCH + b, col e = h*192 + {q,k,v}
__device__ float g_qkv[NROWS * E3];

// fp16 operands for the projection GEMM
__device__ __align__(16) __half g_xh[NROWS * DMODEL];
__device__ __align__(16) __half g_wh[E3 * DMODEL];

// Attention operands: Q hi/lo fp16 (rope + 0.125*log2e), K fp16 (rope), V fp16 [b][h][d][l].
#define QKV_ELEMS (BATCH * NHEADS * L_SEQ * DK)
__device__ __align__(16) __half g_qhi[QKV_ELEMS];
__device__ __align__(16) __half g_qlo[QKV_ELEMS];
__device__ __align__(16) __half g_kh [QKV_ELEMS];
__device__ __align__(16) __half g_vh [QKV_ELEMS];

__constant__ float c_theta[16] = {
    1.0f,                     0.5623413251903491f,     0.31622776601683794f,   0.17782794100389228f,
    0.1f,                     0.05623413251903491f,    0.031622776601683794f,  0.017782794100389228f,
    0.01f,                    0.005623413251903491f,   0.0031622776601683794f, 0.0017782794100389228f,
    0.001f,                   0.0005623413251903491f,  0.00031622776601683794f,0.00017782794100389227f
};

// ---------------------------------------------------------------------------
// Helpers
// ---------------------------------------------------------------------------
#define MMA_F16(C, A, B)                                                         \
    asm volatile("mma.sync.aligned.m16n8k16.row.col.f32.f16.f16.f32 "            \
                 "{%0,%1,%2,%3}, {%4,%5,%6,%7}, {%8,%9}, {%0,%1,%2,%3};"         \
                 : "+f"((C)[0]), "+f"((C)[1]), "+f"((C)[2]), "+f"((C)[3])        \
                 : "r"((A)[0]), "r"((A)[1]), "r"((A)[2]), "r"((A)[3]),           \
                   "r"((B)[0]), "r"((B)[1]))

__device__ __forceinline__ void ldm4(unsigned* r, unsigned a) {
    asm volatile("ldmatrix.sync.aligned.m8n8.x4.shared.b16 {%0,%1,%2,%3}, [%4];"
                 : "=r"(r[0]), "=r"(r[1]), "=r"(r[2]), "=r"(r[3]) : "r"(a));
}

__device__ __forceinline__ float ex2f(float x) {
    float r;
    asm("ex2.approx.ftz.f32 %0, %1;" : "=f"(r) : "f"(x));
    return r;
}

__device__ __forceinline__ void cp16(unsigned s, const void* g) {
    asm volatile("cp.async.ca.shared.global [%0], [%1], 16;" :: "r"(s), "l"(g));
}

__device__ __forceinline__ unsigned smem_u32(const void* p) {
    return (unsigned)__cvta_generic_to_shared(p);
}

__device__ __forceinline__ unsigned pack_h2(float f0, float f1) {
    __half2 h = __floats2half2_rn(f0, f1);
    return *reinterpret_cast<unsigned*>(&h);
}

// ---------------------------------------------------------------------------
// Fused convert kernel: X -> g_xh, W -> g_wh (single fp16 each).
// ---------------------------------------------------------------------------
#define NX4 (NROWS * DMODEL / 4)
#define NW4 (E3 * DMODEL / 4)

__global__ void __launch_bounds__(256) convert_xw(const float* __restrict__ x,
                                                  const float* __restrict__ w) {
    int t = blockIdx.x * 256 + threadIdx.x;
    const float4 v = (t < NX4) ? reinterpret_cast<const float4*>(x)[t]
                               : reinterpret_cast<const float4*>(w)[t - NX4];
    uint2 o = make_uint2(pack_h2(v.x, v.y), pack_h2(v.z, v.w));
    if (t < NX4) reinterpret_cast<uint2*>(g_xh)[t] = o;
    else         reinterpret_cast<uint2*>(g_wh)[t - NX4] = o;
}

// ---------------------------------------------------------------------------
// Kernel 1: QKV projection GEMM (fp16 mma.sync + ldmatrix).
// CTA tile 128x128, BK=32, 8 warps, warp tile 32x64.
// 3-stage ring, single sync per iteration (issue t+2 before compute t).
// ---------------------------------------------------------------------------
#define KPAD 40
#define ARR_B  (128 * KPAD * 2)
#define STG_B  (2 * ARR_B)
#define QKV_SMEM (3 * STG_B)

#define G_ISSUE(KT, ST)                                                               \
    do {                                                                              \
        const int _k0 = (KT) * 32;                                                    \
        _Pragma("unroll")                                                             \
        for (int _arr = 0; _arr < 2; _arr++) {                                        \
            _Pragma("unroll")                                                         \
            for (int _rep = 0; _rep < 2; _rep++) {                                    \
                int _sub = _rep * 256 + tid;                                          \
                int _row = _sub >> 2;                                                 \
                int _ch  = _sub & 3;                                                  \
                unsigned _sp = smem0 + (ST) * STG_B + _arr * ARR_B + _row * (KPAD*2) + _ch * 16; \
                const __half* _gp;                                                    \
                if (_arr == 0) _gp = g_xh + (size_t)(r0 + _row) * DMODEL + _k0 + _ch * 8; \
                else           _gp = g_wh + (size_t)(e0 + _row) * DMODEL + _k0 + _ch * 8; \
                cp16(_sp, _gp);                                                       \
            }                                                                         \
        }                                                                             \
        asm volatile("cp.async.commit_group;");                                       \
    } while (0)

__global__ void __launch_bounds__(256, 2) qkv_gemm_tc() {
    extern __shared__ __align__(16) char qsm[];
    const unsigned smem0 = smem_u32(qsm);

    const int tid   = threadIdx.x;
    const int wid   = tid >> 5;
    const int lane  = tid & 31;
    const int warpM = wid >> 1;
    const int warpN = wid & 1;
    const int r0    = blockIdx.y * 128;
    const int e0    = blockIdx.x * 128;

    const int fr = lane >> 2;
    const int fc = (lane & 3) * 2;

    const int lrA = lane & 15;
    const int lcA = (lane >> 4) << 3;
    const int lrB = (lane & 7) + ((lane >> 4) << 3);
    const int lcB = ((lane >> 3) & 1) << 3;

    float acc[2][8][4] = {};

    G_ISSUE(0, 0);
    G_ISSUE(1, 1);

    for (int kt = 0; kt < 32; kt++) {
        if (kt < 31) asm volatile("cp.async.wait_group 1;");
        else         asm volatile("cp.async.wait_group 0;");
        __syncthreads();
        if (kt + 2 < 32) G_ISSUE(kt + 2, (kt + 2) % 3);

        const int st = kt % 3;
        const unsigned uA = smem0 + st * STG_B;
        const unsigned uB = uA + ARR_B;

#pragma unroll
        for (int ks = 0; ks < 32; ks += 16) {
            unsigned ah[2][4], bh[4][4];
#pragma unroll
            for (int mf = 0; mf < 2; mf++) {
                const unsigned ao = (unsigned)(((warpM * 32 + mf * 16 + lrA) * KPAD + ks + lcA) * 2);
                ldm4(ah[mf], uA + ao);
            }
#pragma unroll
            for (int g4 = 0; g4 < 4; g4++) {
                const unsigned bo = (unsigned)(((warpN * 64 + g4 * 16 + lrB) * KPAD + ks + lcB) * 2);
                ldm4(bh[g4], uB + bo);
            }
#pragma unroll
            for (int mf = 0; mf < 2; mf++)
#pragma unroll
                for (int nf = 0; nf < 8; nf++) {
                    const unsigned* bf = &bh[nf >> 1][(nf & 1) * 2];
                    MMA_F16(acc[mf][nf], ah[mf], bf);
                }
        }
    }

#pragma unroll
    for (int mf = 0; mf < 2; mf++)
#pragma unroll
        for (int nf = 0; nf < 8; nf++) {
            const int row = r0 + warpM * 32 + mf * 16 + fr;
            const int col = e0 + warpN * 64 + nf * 8 + fc;
            *reinterpret_cast<float2*>(&g_qkv[(size_t)row * E3 + col]) =
                make_float2(acc[mf][nf][0], acc[mf][nf][1]);
            *reinterpret_cast<float2*>(&g_qkv[(size_t)(row + 8) * E3 + col]) =
                make_float2(acc[mf][nf][2], acc[mf][nf][3]);
        }
}

// ---------------------------------------------------------------------------
// Kernel 2 (fused prep): blocks [0, 8192): rope+convert Q/K.
//                        blocks [8192, 9216): V transpose+convert (256 thr/tile).
// ---------------------------------------------------------------------------
#define QSCALE 0.1803368801111243f   // 0.125 * log2(e)
#define QK_BLOCKS 8192

__global__ void __launch_bounds__(256) prep_qkv() {
    __shared__ float s[64][68];

    if (blockIdx.x < QK_BLOCKS) {
        // ---- rope + convert Q/K ----
        const int t   = blockIdx.x * 256 + threadIdx.x;
        const int j   = t & 15;
        const int sqk = (t >> 4) & 1;
        const int h   = (t >> 5) & 15;
        const int r   = t >> 9;
        const int l   = r >> 1;
        const int b   = r & 1;

        const float* base = g_qkv + (size_t)r * E3 + h * 192 + sqk * 64;
        float x0 = base[j];
        float x1 = base[j + 16];
        float p0 = base[j + 32];
        float p1 = base[j + 48];

        float ang = (float)l * c_theta[j];
        float sn, cs;
        sincosf(ang, &sn, &cs);
        float y0 = x0 * cs - x1 * sn;
        float y1 = x1 * cs + x0 * sn;

        const size_t dst = ((size_t)(b * NHEADS + h) * L_SEQ + l) * DK;
        float vals[4] = {y0, y1, p0, p1};
        int   ds[4]   = {j, j + 16, j + 32, j + 48};

        if (sqk == 0) {
#pragma unroll
            for (int i = 0; i < 4; i++) {
                float v = vals[i] * QSCALE;
                __half hi = __float2half_rn(v);
                g_qhi[dst + ds[i]] = hi;
                g_qlo[dst + ds[i]] = __float2half_rn(v - __half2float(hi));
            }
        } else {
#pragma unroll
            for (int i = 0; i < 4; i++)
                g_kh[dst + ds[i]] = __float2half_rn(vals[i]);
        }
    } else {
        // ---- V transpose + convert ----
        const int vb   = blockIdx.x - QK_BLOCKS;       // 0..1023
        const int tile = vb & 31;
        const int h    = (vb >> 5) & 15;
        const int b    = vb >> 9;
        const int tid  = threadIdx.x;

#pragma unroll
        for (int i = 0; i < 4; i++) {
            int id  = i * 256 + tid;
            int row = id >> 4;
            int c4  = id & 15;
            const float* g = g_qkv + (size_t)((tile * 64 + row) * 2 + b) * E3 + h * 192 + 128 + c4 * 4;
            float4 v = *reinterpret_cast<const float4*>(g);
            s[row][c4 * 4 + 0] = v.x; s[row][c4 * 4 + 1] = v.y;
            s[row][c4 * 4 + 2] = v.z; s[row][c4 * 4 + 3] = v.w;
        }
        __syncthreads();

        const int d = tid & 63, part = tid >> 6;   // part 0..3, 16 rows each
        const size_t ob = ((size_t)(b * NHEADS + h) * DK + d) * L_SEQ + tile * 64 + part * 16;

#pragma unroll
        for (int kc = 0; kc < 2; kc++) {
            unsigned hw[4];
#pragma unroll
            for (int p = 0; p < 4; p++)
                hw[p] = pack_h2(s[part * 16 + kc * 8 + p * 2 + 0][d],
                                s[part * 16 + kc * 8 + p * 2 + 1][d]);
            *reinterpret_cast<uint4*>(g_vh + ob + kc * 8) = make_uint4(hw[0], hw[1], hw[2], hw[3]);
        }
    }
}

// ---------------------------------------------------------------------------
// Kernel 3: fp16 tensor-core flash attention.
// S = (Qhi + Qlo) Kh^T ; O += Ph Vh.
// 3-stage KV ring, single sync/tile (issue t+2 before compute t).
// smem: Q 36,864 B + 3 stages x 18,432 B = 92,160 B -> 2 CTAs/SM.
// ---------------------------------------------------------------------------
#define ATTN_SMEM_BYTES ((18432 + 3 * 9216) * 2)   // 92160

__global__ void __launch_bounds__(128, 2) attn_tc(float* __restrict__ out) {
    extern __shared__ __align__(16) __half sm[];
    const unsigned smem_base = smem_u32(sm);

    const int tid  = threadIdx.x;
    const int w    = tid >> 5;
    const int lane = tid & 31;
    const int g    = lane >> 2;
    const int tg   = lane & 3;

    const int lrA = lane & 15;
    const int lcA = (lane >> 4) << 3;
    const int lrB = (lane & 7) + ((lane >> 4) << 3);
    const int lcB = ((lane >> 3) & 1) << 3;

    const int q0 = blockIdx.x * 128;
    const int h  = blockIdx.y;
    const int b  = blockIdx.z;
    const int hb = b * NHEADS + h;

    const size_t qkbase = (size_t)hb * L_SEQ * DK;
    const size_t vbase  = (size_t)hb * DK * L_SEQ;

#pragma unroll
    for (int i = 0; i < 16; i++) {
        int id  = i * 128 + tid;
        int rid = (id >> 3) & 127;
        int ch  = id & 7;
        const __half* gp = (i < 8 ? g_qhi : g_qlo) + qkbase + (size_t)(q0 + rid) * DK + ch * 8;
        unsigned sp = smem_base + ((i < 8 ? 0 : 9216) + rid * 72 + ch * 8) * 2;
        cp16(sp, gp);
    }
    asm volatile("cp.async.commit_group;");

#define ISSUE_TILE(T, BUF)                                                            \
    do {                                                                              \
        _Pragma("unroll")                                                             \
        for (int i = 0; i < 8; i++) {                                                 \
            int id  = i * 128 + tid;                                                  \
            int arr = i >> 2;                                                         \
            int rid = (id >> 3) & 63;                                                 \
            int ch  = id & 7;                                                         \
            const __half* gp;                                                         \
            if (arr == 0) gp = g_kh + qkbase + (size_t)((T) * 64 + rid) * DK + ch * 8; \
            else          gp = g_vh + vbase + (size_t)rid * L_SEQ + (T) * 64 + ch * 8; \
            unsigned sp = smem_base + (18432 + (BUF) * 9216 + arr * 4608 + rid * 72 + ch * 8) * 2; \
            cp16(sp, gp);                                                             \
        }                                                                             \
        asm volatile("cp.async.commit_group;");                                       \
    } while (0)

    ISSUE_TILE(0, 0);
    ISSUE_TILE(1, 1);

    float o[2][8][4] = {};
    float mrow[2][2] = {{-1e30f, -1e30f}, {-1e30f, -1e30f}};
    float lrow[2][2] = {};

    const int rb0 = w * 32;

    for (int t = 0; t < 32; t++) {
        if (t < 31) asm volatile("cp.async.wait_group 1;");
        else        asm volatile("cp.async.wait_group 0;");
        __syncthreads();
        if (t + 2 < 32) ISSUE_TILE(t + 2, (t + 2) % 3);

        const int st = t % 3;
        const unsigned uQh = smem_base;
        const unsigned uQl = smem_base + 9216 * 2;
        const unsigned uKh = smem_base + (18432 + st * 9216) * 2;
        const unsigned uVh = uKh + 4608 * 2;

        // ---- S = (Qhi + Qlo) Kh^T ----
        float s[2][8][4] = {};
#pragma unroll
        for (int kf = 0; kf < 4; kf++) {
            unsigned ah[2][4], al[2][4], kh[4][4];
#pragma unroll
            for (int mf = 0; mf < 2; mf++) {
                const unsigned ao = (unsigned)(((rb0 + mf * 16 + lrA) * 72 + kf * 16 + lcA) * 2);
                ldm4(ah[mf], uQh + ao);
                ldm4(al[mf], uQl + ao);
            }
#pragma unroll
            for (int g4 = 0; g4 < 4; g4++) {
                const unsigned bo = (unsigned)(((g4 * 16 + lrB) * 72 + kf * 16 + lcB) * 2);
                ldm4(kh[g4], uKh + bo);
            }
#pragma unroll
            for (int nf = 0; nf < 8; nf++) {
                const unsigned* bf = &kh[nf >> 1][(nf & 1) * 2];
#pragma unroll
                for (int mf = 0; mf < 2; mf++) {
                    MMA_F16(s[mf][nf], ah[mf], bf);
                    MMA_F16(s[mf][nf], al[mf], bf);
                }
            }
        }

        // ---- online softmax (log2 domain) ----
        unsigned ph[2][4][4];
#pragma unroll
        for (int mf = 0; mf < 2; mf++) {
            float mx0 = -1e30f, mx1 = -1e30f;
#pragma unroll
            for (int nf = 0; nf < 8; nf++) {
                mx0 = fmaxf(mx0, fmaxf(s[mf][nf][0], s[mf][nf][1]));
                mx1 = fmaxf(mx1, fmaxf(s[mf][nf][2], s[mf][nf][3]));
            }
            mx0 = fmaxf(mx0, __shfl_xor_sync(0xffffffffu, mx0, 1));
            mx0 = fmaxf(mx0, __shfl_xor_sync(0xffffffffu, mx0, 2));
            mx1 = fmaxf(mx1, __shfl_xor_sync(0xffffffffu, mx1, 1));
            mx1 = fmaxf(mx1, __shfl_xor_sync(0xffffffffu, mx1, 2));

            float mn0 = fmaxf(mrow[mf][0], mx0);
            float mn1 = fmaxf(mrow[mf][1], mx1);
            float sc0 = ex2f(mrow[mf][0] - mn0);
            float sc1 = ex2f(mrow[mf][1] - mn1);
            mrow[mf][0] = mn0;
            mrow[mf][1] = mn1;

            float rs0 = 0.f, rs1 = 0.f;
#pragma unroll
            for (int nf = 0; nf < 8; nf++) {
                s[mf][nf][0] = ex2f(s[mf][nf][0] - mn0);
                s[mf][nf][1] = ex2f(s[mf][nf][1] - mn0);
                s[mf][nf][2] = ex2f(s[mf][nf][2] - mn1);
                s[mf][nf][3] = ex2f(s[mf][nf][3] - mn1);
                rs0 += s[mf][nf][0] + s[mf][nf][1];
                rs1 += s[mf][nf][2] + s[mf][nf][3];
            }
            rs0 += __shfl_xor_sync(0xffffffffu, rs0, 1);
            rs0 += __shfl_xor_sync(0xffffffffu, rs0, 2);
            rs1 += __shfl_xor_sync(0xffffffffu, rs1, 1);
            rs1 += __shfl_xor_sync(0xffffffffu, rs1, 2);
            lrow[mf][0] = lrow[mf][0] * sc0 + rs0;
            lrow[mf][1] = lrow[mf][1] * sc1 + rs1;

#pragma unroll
            for (int nf = 0; nf < 8; nf++) {
                o[mf][nf][0] *= sc0; o[mf][nf][1] *= sc0;
                o[mf][nf][2] *= sc1; o[mf][nf][3] *= sc1;
            }

#pragma unroll
            for (int kf = 0; kf < 4; kf++) {
                const int n0 = 2 * kf, n1 = 2 * kf + 1;
                ph[mf][kf][0] = pack_h2(s[mf][n0][0], s[mf][n0][1]);
                ph[mf][kf][1] = pack_h2(s[mf][n0][2], s[mf][n0][3]);
                ph[mf][kf][2] = pack_h2(s[mf][n1][0], s[mf][n1][1]);
                ph[mf][kf][3] = pack_h2(s[mf][n1][2], s[mf][n1][3]);
            }
        }

        // ---- O += Ph Vh ----
#pragma unroll
        for (int kf = 0; kf < 4; kf++) {
            unsigned vh[4][4];
#pragma unroll
            for (int g4 = 0; g4 < 4; g4++) {
                const unsigned bo = (unsigned)(((g4 * 16 + lrB) * 72 + kf * 16 + lcB) * 2);
                ldm4(vh[g4], uVh + bo);
            }
#pragma unroll
            for (int nf = 0; nf < 8; nf++) {
                const unsigned* bf = &vh[nf >> 1][(nf & 1) * 2];
#pragma unroll
                for (int mf = 0; mf < 2; mf++)
                    MMA_F16(o[mf][nf], ph[mf][kf], bf);
            }
        }
    }

    // ---- epilogue: out[l][b][h*64 + d] ----
#pragma unroll
    for (int mf = 0; mf < 2; mf++) {
        const float inv0 = 1.0f / lrow[mf][0];
        const float inv1 = 1.0f / lrow[mf][1];
        const int r0 = q0 + rb0 + mf * 16 + g;
#pragma unroll
        for (int nf = 0; nf < 8; nf++) {
            const int col = h * 64 + nf * 8 + tg * 2;
            *reinterpret_cast<float2*>(out + (size_t)(r0 * 2 + b) * DMODEL + col) =
                make_float2(o[mf][nf][0] * inv0, o[mf][nf][1] * inv0);
            *reinterpret_cast<float2*>(out + (size_t)((r0 + 8) * 2 + b) * DMODEL + col) =
                make_float2(o[mf][nf][2] * inv1, o[mf][nf][3] * inv1);
        }
    }
}

// ---------------------------------------------------------------------------
extern "C" void kernel_launch(void* const* d_in, const int* in_sizes, int n_in,
                              void* d_out, int out_size) {
    const float* x = (const float*)d_in[0];
    const float* w = (const float*)d_in[1];
    if (n_in >= 2 && in_sizes[0] == E3 * DMODEL && in_sizes[1] == NROWS * DMODEL) {
        const float* t = x; x = w; w = t;
    }
    float* out = (float*)d_out;

    static bool attr_set = false;
    if (!attr_set) {
        cudaFuncSetAttribute(attn_tc, cudaFuncAttributeMaxDynamicSharedMemorySize,
                             ATTN_SMEM_BYTES);
        cudaFuncSetAttribute(qkv_gemm_tc, cudaFuncAttributeMaxDynamicSharedMemorySize,
                             QKV_SMEM);
        attr_set = true;
    }

    convert_xw<<<(NX4 + NW4) / 256, 256>>>(x, w);
    qkv_gemm_tc<<<dim3(E3 / 128, NROWS / 128), 256, QKV_SMEM>>>();
    prep_qkv<<<QK_BLOCKS + 1024, 256>>>();
    attn_tc<<<dim3(L_SEQ / 128, NHEADS, BATCH), 128, ATTN_SMEM_BYTES>>>(out);
}